// round 2
// baseline (speedup 1.0000x reference)
#include <cuda_runtime.h>
#include <math.h>

// Problem dims (fixed)
#define NB   8
#define NS   1024
#define NH   16
#define NDK  64
#define FDEC 1024
#define FD   16      // decode output features
#define KIN  784     // 16 traj features + 768 latent
#define MROWS (NB*NS)   // 8192

// ---------------- scratch (static __device__, no allocation) ----------------
__device__ float g_xcat[MROWS * KIN];
__device__ float g_x   [MROWS * FDEC];
__device__ float g_xn  [MROWS * FDEC];
__device__ float g_q   [MROWS * FDEC];
__device__ float g_k   [MROWS * FDEC];
__device__ float g_v   [MROWS * FDEC];
__device__ float g_o   [MROWS * FDEC];
__device__ float g_x2  [MROWS * FDEC];

// ---------------- concat(r_traj, broadcast z) -> xcat [8192, 784] -----------
__global__ void __launch_bounds__(256) concat_k(
    const float* __restrict__ r, const float* __restrict__ z,
    float* __restrict__ xcat)
{
    int idx = blockIdx.x * 256 + threadIdx.x;
    if (idx >= MROWS * KIN) return;
    int m = idx / KIN, f = idx - m * KIN;
    int b = m >> 10;
    xcat[idx] = (f < 16) ? r[m * 16 + f] : z[b * 768 + (f - 16)];
}

// ---------------- LayerNorm over last dim (1024), two-pass -------------------
__device__ __forceinline__ float blockReduce(float val, float* sh)
{
    __syncthreads();
    int lane = threadIdx.x & 31, wid = threadIdx.x >> 5;
    #pragma unroll
    for (int o = 16; o; o >>= 1) val += __shfl_xor_sync(0xffffffffu, val, o);
    if (lane == 0) sh[wid] = val;
    __syncthreads();
    if (wid == 0) {
        val = (lane < 8) ? sh[lane] : 0.f;
        #pragma unroll
        for (int o = 4; o; o >>= 1) val += __shfl_xor_sync(0xffffffffu, val, o);
        if (lane == 0) sh[0] = val;
    }
    __syncthreads();
    return sh[0];
}

__global__ void __launch_bounds__(256) ln_k(
    const float* __restrict__ x, const float* __restrict__ g,
    const float* __restrict__ beta, float* __restrict__ xn)
{
    __shared__ float red[32];
    int row = blockIdx.x;
    float4 v = ((const float4*)(x + (size_t)row * 1024))[threadIdx.x];
    float s = blockReduce(v.x + v.y + v.z + v.w, red);
    float mean = s * (1.0f / 1024.0f);
    float dx = v.x - mean, dy = v.y - mean, dz = v.z - mean, dw = v.w - mean;
    float s2 = blockReduce(dx*dx + dy*dy + dz*dz + dw*dw, red);
    float inv = rsqrtf(s2 * (1.0f / 1024.0f) + 1e-6f);
    float4 gg = ((const float4*)g)[threadIdx.x];
    float4 bb = ((const float4*)beta)[threadIdx.x];
    float4 o;
    o.x = gg.x * dx * inv + bb.x;
    o.y = gg.y * dy * inv + bb.y;
    o.z = gg.z * dz * inv + bb.z;
    o.w = gg.w * dw * inv + bb.w;
    ((float4*)(xn + (size_t)row * 1024))[threadIdx.x] = o;
}

// ---------------- tiled SGEMM: C = A[M,K] @ B[N,K]^T + bias ------------------
// MODE 0: plain   C[m*N+n]
// MODE 1: qkv scatter -> [B,H,S,DK]
// MODE 2: residual add (res[m*N+n] + ...)
template<int MODE>
__global__ void __launch_bounds__(256) sgemm_k(
    const float* __restrict__ A, const float* __restrict__ Bw,
    const float* __restrict__ bias, const float* __restrict__ res,
    float* __restrict__ C, int M, int N, int K)
{
    __shared__ float As[8][128];
    __shared__ float Bs[8][128];
    const int tid = threadIdx.x;
    const int bm = blockIdx.y * 128, bn = blockIdx.x * 128;
    const int lr = tid >> 1, lk = (tid & 1) << 2;
    const float* Ap = A  + (size_t)(bm + lr) * K + lk;
    const float* Bp = Bw + (size_t)(bn + lr) * K + lk;
    const int tx = tid & 15, ty = tid >> 4;

    float acc[8][8];
    #pragma unroll
    for (int i = 0; i < 8; i++)
        #pragma unroll
        for (int j = 0; j < 8; j++) acc[i][j] = 0.f;

    for (int k0 = 0; k0 < K; k0 += 8) {
        float4 a4 = *(const float4*)(Ap + k0);
        float4 b4 = *(const float4*)(Bp + k0);
        As[lk+0][lr] = a4.x; As[lk+1][lr] = a4.y; As[lk+2][lr] = a4.z; As[lk+3][lr] = a4.w;
        Bs[lk+0][lr] = b4.x; Bs[lk+1][lr] = b4.y; Bs[lk+2][lr] = b4.z; Bs[lk+3][lr] = b4.w;
        __syncthreads();
        #pragma unroll
        for (int k = 0; k < 8; k++) {
            float a[8], b[8];
            *(float4*)(a)     = *(const float4*)&As[k][ty * 8];
            *(float4*)(a + 4) = *(const float4*)&As[k][ty * 8 + 4];
            *(float4*)(b)     = *(const float4*)&Bs[k][tx * 8];
            *(float4*)(b + 4) = *(const float4*)&Bs[k][tx * 8 + 4];
            #pragma unroll
            for (int i = 0; i < 8; i++)
                #pragma unroll
                for (int j = 0; j < 8; j++)
                    acc[i][j] = fmaf(a[i], b[j], acc[i][j]);
        }
        __syncthreads();
    }

    #pragma unroll
    for (int i = 0; i < 8; i++) {
        int m = bm + ty * 8 + i;
        #pragma unroll
        for (int j = 0; j < 8; j++) {
            int n = bn + tx * 8 + j;
            float val = acc[i][j] + bias[n];
            if (MODE == 0) {
                C[(size_t)m * N + n] = val;
            } else if (MODE == 1) {
                int b = m >> 10, s = m & 1023, h = n >> 6, d = n & 63;
                C[(size_t)(((b << 4) + h) * 1024 + s) * 64 + d] = val;
            } else { // MODE 2
                C[(size_t)m * N + n] = res[(size_t)m * N + n] + val;
            }
        }
    }
}

// ---------------- final decode: out[b,n,s] = x2[m] . dec_w[n] + dec_b[n] -----
// dec_w is [16, 1024]; output is [B, 16, S]. One block per row m, warp n
// computes output feature n.
__global__ void __launch_bounds__(512) dec_k(
    const float* __restrict__ x2, const float* __restrict__ w,
    const float* __restrict__ bias, float* __restrict__ out)
{
    const int m = blockIdx.x;             // 0..8191
    const int b = m >> 10, s = m & 1023;
    const int n = threadIdx.x >> 5;       // 0..15
    const int lane = threadIdx.x & 31;
    const float4* xr = (const float4*)(x2 + (size_t)m * FDEC);
    const float4* wr = (const float4*)(w  + (size_t)n * FDEC);
    float sum = 0.f;
    #pragma unroll
    for (int i = 0; i < 8; i++) {
        float4 a  = xr[lane + i * 32];
        float4 ww = wr[lane + i * 32];
        sum += a.x * ww.x + a.y * ww.y + a.z * ww.z + a.w * ww.w;
    }
    #pragma unroll
    for (int o = 16; o; o >>= 1) sum += __shfl_xor_sync(0xffffffffu, sum, o);
    if (lane == 0)
        out[(size_t)(b * FD + n) * NS + s] = sum + bias[n];
}

// ---------------- flash-style causal attention with ALiBi --------------------
// q,k,v: [B,H,S,DK] contiguous.  o written as [B,S,H*DK].
// block: 128 threads, handles 64 query rows of one (b,h). KV chunks of 64.
#define PAD 68
#define ATTN_SMEM (4 * 64 * PAD * (int)sizeof(float))   // Qs,Ks,Vs,Ss

__global__ void __launch_bounds__(128) attn_k(
    const float* __restrict__ q, const float* __restrict__ k,
    const float* __restrict__ v, float* __restrict__ o)
{
    extern __shared__ float sm[];
    float* Qs = sm;
    float* Ks = Qs + 64 * PAD;
    float* Vs = Ks + 64 * PAD;
    float* Ss = Vs + 64 * PAD;

    const int b = blockIdx.z, h = blockIdx.y, qc = blockIdx.x;
    const int tid = threadIdx.x;
    const int lrow = tid >> 1, lcol0 = (tid & 1) * 32;
    const int tx = tid & 7, ty = tid >> 3;       // tx: 8 d-col groups, ty: 16 row groups

    const size_t head = (size_t)(b * NH + h) * NS * NDK;
    const float* qb = q + head;
    const float* kb = k + head;
    const float* vb = v + head;

    // load Q chunk (scaled by 1/sqrt(DK) = 0.125)
    {
        const float* src = qb + (size_t)(qc * 64 + lrow) * 64 + lcol0;
        float* dst = Qs + lrow * PAD + lcol0;
        #pragma unroll
        for (int c = 0; c < 32; c += 4) {
            float4 t = *(const float4*)(src + c);
            t.x *= 0.125f; t.y *= 0.125f; t.z *= 0.125f; t.w *= 0.125f;
            *(float4*)(dst + c) = t;
        }
    }

    const float slope = exp2f(-0.5f * (float)(h + 1));
    float m_r[4], l_r[4], Oa[4][8];
    #pragma unroll
    for (int r = 0; r < 4; r++) {
        m_r[r] = -1e30f; l_r[r] = 0.f;
        #pragma unroll
        for (int c = 0; c < 8; c++) Oa[r][c] = 0.f;
    }

    const int ibase = qc * 64 + ty * 4;

    for (int kc = 0; kc <= qc; kc++) {
        // load K, V chunk
        {
            const float* ks = kb + (size_t)(kc * 64 + lrow) * 64 + lcol0;
            const float* vs = vb + (size_t)(kc * 64 + lrow) * 64 + lcol0;
            float* kd = Ks + lrow * PAD + lcol0;
            float* vd = Vs + lrow * PAD + lcol0;
            #pragma unroll
            for (int c = 0; c < 32; c += 4) {
                *(float4*)(kd + c) = *(const float4*)(ks + c);
                *(float4*)(vd + c) = *(const float4*)(vs + c);
            }
        }
        __syncthreads();

        // phase 1: S tile (4 rows x 8 cols per thread)
        float s_[4][8];
        #pragma unroll
        for (int r = 0; r < 4; r++)
            #pragma unroll
            for (int j = 0; j < 8; j++) s_[r][j] = 0.f;

        #pragma unroll
        for (int d = 0; d < 64; d += 4) {
            float qa[4][4], kv_[8][4];
            #pragma unroll
            for (int r = 0; r < 4; r++) {
                float4 t = *(const float4*)&Qs[(ty * 4 + r) * PAD + d];
                qa[r][0]=t.x; qa[r][1]=t.y; qa[r][2]=t.z; qa[r][3]=t.w;
            }
            #pragma unroll
            for (int j = 0; j < 8; j++) {
                float4 t = *(const float4*)&Ks[(tx * 8 + j) * PAD + d];
                kv_[j][0]=t.x; kv_[j][1]=t.y; kv_[j][2]=t.z; kv_[j][3]=t.w;
            }
            #pragma unroll
            for (int r = 0; r < 4; r++)
                #pragma unroll
                for (int j = 0; j < 8; j++)
                    #pragma unroll
                    for (int dd = 0; dd < 4; dd++)
                        s_[r][j] = fmaf(qa[r][dd], kv_[j][dd], s_[r][j]);
        }

        // bias + online softmax
        const int jbase = kc * 64 + tx * 8;
        #pragma unroll
        for (int r = 0; r < 4; r++) {
            int ig = ibase + r;
            float mx = -1e30f;
            #pragma unroll
            for (int j = 0; j < 8; j++) {
                int jg = jbase + j;
                float val = s_[r][j] + slope * (float)jg;
                if (jg > ig) val -= 1e9f;
                s_[r][j] = val;
                mx = fmaxf(mx, val);
            }
            mx = fmaxf(mx, __shfl_xor_sync(0xffffffffu, mx, 1));
            mx = fmaxf(mx, __shfl_xor_sync(0xffffffffu, mx, 2));
            mx = fmaxf(mx, __shfl_xor_sync(0xffffffffu, mx, 4));
            float mnew = fmaxf(m_r[r], mx);
            float corr = __expf(m_r[r] - mnew);
            m_r[r] = mnew;
            float rs = 0.f;
            #pragma unroll
            for (int j = 0; j < 8; j++) {
                float p = __expf(s_[r][j] - mnew);
                rs += p;
                Ss[(ty * 4 + r) * PAD + tx * 8 + j] = p;
            }
            rs += __shfl_xor_sync(0xffffffffu, rs, 1);
            rs += __shfl_xor_sync(0xffffffffu, rs, 2);
            rs += __shfl_xor_sync(0xffffffffu, rs, 4);
            l_r[r] = l_r[r] * corr + rs;
            #pragma unroll
            for (int c = 0; c < 8; c++) Oa[r][c] *= corr;
        }
        __syncthreads();

        // phase 2: O += P @ V  (full j range from Ss)
        #pragma unroll
        for (int j = 0; j < 64; j += 4) {
            float pr[4][4];
            #pragma unroll
            for (int r = 0; r < 4; r++) {
                float4 t = *(const float4*)&Ss[(ty * 4 + r) * PAD + j];
                pr[r][0]=t.x; pr[r][1]=t.y; pr[r][2]=t.z; pr[r][3]=t.w;
            }
            #pragma unroll
            for (int jj = 0; jj < 4; jj++) {
                float vv[8];
                *(float4*)(vv)     = *(const float4*)&Vs[(j + jj) * PAD + tx * 8];
                *(float4*)(vv + 4) = *(const float4*)&Vs[(j + jj) * PAD + tx * 8 + 4];
                #pragma unroll
                for (int r = 0; r < 4; r++)
                    #pragma unroll
                    for (int c = 0; c < 8; c++)
                        Oa[r][c] = fmaf(pr[r][jj], vv[c], Oa[r][c]);
            }
        }
        __syncthreads();
    }

    // write o in [B,S,H*DK] layout
    #pragma unroll
    for (int r = 0; r < 4; r++) {
        int sg = ibase + r;
        float inv = 1.0f / l_r[r];
        float* dst = o + (size_t)(b * NS + sg) * (NH * NDK) + h * NDK + tx * 8;
        #pragma unroll
        for (int c = 0; c < 8; c++) dst[c] = Oa[r][c] * inv;
    }
}

// ---------------- launcher ----------------------------------------------------
extern "C" void kernel_launch(void* const* d_in, const int* in_sizes, int n_in,
                              void* d_out, int out_size)
{
    const float* z   = (const float*)d_in[0];
    const float* r   = (const float*)d_in[1];
    const float* dwn = (const float*)d_in[2];
    const float* dbn = (const float*)d_in[3];
    const float* lng = (const float*)d_in[4];
    const float* lnb = (const float*)d_in[5];
    const float* wq  = (const float*)d_in[6];
    const float* bq  = (const float*)d_in[7];
    const float* wk  = (const float*)d_in[8];
    const float* bk  = (const float*)d_in[9];
    const float* wv  = (const float*)d_in[10];
    const float* bv  = (const float*)d_in[11];
    const float* wo  = (const float*)d_in[12];
    const float* bo  = (const float*)d_in[13];
    const float* dcw = (const float*)d_in[14];
    const float* dcb = (const float*)d_in[15];
    float* out = (float*)d_out;

    float *xcat, *x, *xn, *q, *k, *v, *o, *x2;
    cudaGetSymbolAddress((void**)&xcat, g_xcat);
    cudaGetSymbolAddress((void**)&x,    g_x);
    cudaGetSymbolAddress((void**)&xn,   g_xn);
    cudaGetSymbolAddress((void**)&q,    g_q);
    cudaGetSymbolAddress((void**)&k,    g_k);
    cudaGetSymbolAddress((void**)&v,    g_v);
    cudaGetSymbolAddress((void**)&o,    g_o);
    cudaGetSymbolAddress((void**)&x2,   g_x2);

    // 1) concat
    concat_k<<<(MROWS * KIN + 255) / 256, 256>>>(r, z, xcat);
    // 2) dense: x = xcat @ dense_w^T + b   (M=8192, N=1024, K=784)
    sgemm_k<0><<<dim3(8, 64), 256>>>(xcat, dwn, dbn, nullptr, x, MROWS, FDEC, KIN);
    // 3) LayerNorm
    ln_k<<<MROWS, 256>>>(x, lng, lnb, xn);
    // 4) Q/K/V projections -> [B,H,S,DK]
    sgemm_k<1><<<dim3(8, 64), 256>>>(xn, wq, bq, nullptr, q, MROWS, FDEC, FDEC);
    sgemm_k<1><<<dim3(8, 64), 256>>>(xn, wk, bk, nullptr, k, MROWS, FDEC, FDEC);
    sgemm_k<1><<<dim3(8, 64), 256>>>(xn, wv, bv, nullptr, v, MROWS, FDEC, FDEC);
    // 5) attention
    cudaFuncSetAttribute(attn_k, cudaFuncAttributeMaxDynamicSharedMemorySize, ATTN_SMEM);
    attn_k<<<dim3(NS / 64, NH, NB), 128, ATTN_SMEM>>>(q, k, v, o);
    // 6) x2 = x + o @ wo^T + bo
    sgemm_k<2><<<dim3(8, 64), 256>>>(o, wo, bo, x, x2, MROWS, FDEC, FDEC);
    // 7) out[b,n,s] = (x2 @ dec_w^T + dec_b)[b,s,n] transposed; dec_w is [16,1024]
    dec_k<<<MROWS, 512>>>(x2, dcw, dcb, out);
}

// round 6
// speedup vs baseline: 1.4355x; 1.4355x over previous
#include <cuda_runtime.h>
#include <cuda_bf16.h>
#include <cstdint>
#include <math.h>

// Problem dims (fixed)
#define NB   8
#define NS   1024
#define NH   16
#define NDK  64
#define FDEC 1024
#define FD   16
#define KINR 784          // real K of dense input (16 + 768)
#define KP   1024         // padded K for all GEMMs
#define MROWS (NB*NS)     // 8192

// ---------------- scratch (static __device__, no allocation) ----------------
__device__ float g_x   [MROWS * FDEC];   // dense output (residual source)
__device__ float g_q   [MROWS * FDEC];
__device__ float g_k   [MROWS * FDEC];
__device__ float g_v   [MROWS * FDEC];
__device__ float g_x2  [MROWS * FDEC];

__device__ __nv_bfloat16 g_xc_h[MROWS * KP], g_xc_l[MROWS * KP];
__device__ __nv_bfloat16 g_xn_h[MROWS * KP], g_xn_l[MROWS * KP];
__device__ __nv_bfloat16 g_o_h [MROWS * KP], g_o_l [MROWS * KP];

__device__ __nv_bfloat16 g_wd_h[FDEC * KP], g_wd_l[FDEC * KP];
__device__ __nv_bfloat16 g_wq_h[FDEC * KP], g_wq_l[FDEC * KP];
__device__ __nv_bfloat16 g_wk_h[FDEC * KP], g_wk_l[FDEC * KP];
__device__ __nv_bfloat16 g_wv_h[FDEC * KP], g_wv_l[FDEC * KP];
__device__ __nv_bfloat16 g_wo_h[FDEC * KP], g_wo_l[FDEC * KP];

// ---------------- PTX helpers (sm_80-level: mma.sync / ldmatrix / cp.async) --
__device__ __forceinline__ uint32_t smem_u32(const void* p) {
    uint32_t a;
    asm("{ .reg .u64 t; cvta.to.shared.u64 t, %1; cvt.u32.u64 %0, t; }" : "=r"(a) : "l"(p));
    return a;
}

#define LDSM4(R, A) \
    asm volatile("ldmatrix.sync.aligned.m8n8.x4.shared.b16 {%0,%1,%2,%3}, [%4];" \
        : "=r"((R)[0]), "=r"((R)[1]), "=r"((R)[2]), "=r"((R)[3]) : "r"(A))

#define MMA_BF16(C, A, B0, B1) \
    asm volatile("mma.sync.aligned.m16n8k16.row.col.f32.bf16.bf16.f32 " \
        "{%0,%1,%2,%3},{%4,%5,%6,%7},{%8,%9},{%0,%1,%2,%3};" \
        : "+f"((C)[0]), "+f"((C)[1]), "+f"((C)[2]), "+f"((C)[3]) \
        : "r"((A)[0]), "r"((A)[1]), "r"((A)[2]), "r"((A)[3]), "r"(B0), "r"(B1))

__device__ __forceinline__ void cpa16(uint32_t dst, const void* src) {
    asm volatile("cp.async.cg.shared.global [%0], [%1], 16;" :: "r"(dst), "l"(src));
}
#define CP_COMMIT() asm volatile("cp.async.commit_group;" ::: "memory")
#define CP_WAIT(n)  asm volatile("cp.async.wait_group %0;" :: "n"(n) : "memory")

// ---------------- fp32 -> (hi, lo) bf16 split --------------------------------
__device__ __forceinline__ void split2(float v, __nv_bfloat16& h, __nv_bfloat16& l) {
    h = __float2bfloat16(v);
    l = __float2bfloat16(v - __bfloat162float(h));
}

// concat(r_traj, z, pad) -> xc hi/lo [8192, 1024]
__global__ void __launch_bounds__(256) concat_split_k(
    const float* __restrict__ r, const float* __restrict__ z,
    __nv_bfloat16* __restrict__ hi, __nv_bfloat16* __restrict__ lo)
{
    int idx = blockIdx.x * 256 + threadIdx.x;
    if (idx >= MROWS * KP) return;
    int m = idx >> 10, f = idx & 1023;
    float v = (f < 16) ? r[m * 16 + f]
            : (f < KINR) ? z[(m >> 10) * 768 + (f - 16)] : 0.f;
    split2(v, hi[idx], lo[idx]);
}

// weight split with K padding: w [1024, Ksrc] -> hi/lo [1024, 1024]
__global__ void __launch_bounds__(256) wsplit_k(
    const float* __restrict__ w, __nv_bfloat16* __restrict__ hi,
    __nv_bfloat16* __restrict__ lo, int Ksrc)
{
    int idx = blockIdx.x * 256 + threadIdx.x;
    if (idx >= FDEC * KP) return;
    int n = idx >> 10, k = idx & 1023;
    float v = (k < Ksrc) ? w[n * Ksrc + k] : 0.f;
    split2(v, hi[idx], lo[idx]);
}

// ---------------- LayerNorm (fp32 in, bf16 hi/lo out) ------------------------
__device__ __forceinline__ float blockReduce(float val, float* sh)
{
    __syncthreads();
    int lane = threadIdx.x & 31, wid = threadIdx.x >> 5;
    #pragma unroll
    for (int o = 16; o; o >>= 1) val += __shfl_xor_sync(0xffffffffu, val, o);
    if (lane == 0) sh[wid] = val;
    __syncthreads();
    if (wid == 0) {
        val = (lane < 8) ? sh[lane] : 0.f;
        #pragma unroll
        for (int o = 4; o; o >>= 1) val += __shfl_xor_sync(0xffffffffu, val, o);
        if (lane == 0) sh[0] = val;
    }
    __syncthreads();
    return sh[0];
}

__global__ void __launch_bounds__(256) ln_k(
    const float* __restrict__ x, const float* __restrict__ g,
    const float* __restrict__ beta,
    __nv_bfloat16* __restrict__ xnh, __nv_bfloat16* __restrict__ xnl)
{
    __shared__ float red[32];
    int row = blockIdx.x;
    float4 v = ((const float4*)(x + (size_t)row * 1024))[threadIdx.x];
    float s = blockReduce(v.x + v.y + v.z + v.w, red);
    float mean = s * (1.0f / 1024.0f);
    float dx = v.x - mean, dy = v.y - mean, dz = v.z - mean, dw = v.w - mean;
    float s2 = blockReduce(dx*dx + dy*dy + dz*dz + dw*dw, red);
    float inv = rsqrtf(s2 * (1.0f / 1024.0f) + 1e-6f);
    float4 gg = ((const float4*)g)[threadIdx.x];
    float4 bb = ((const float4*)beta)[threadIdx.x];
    size_t base = (size_t)row * 1024 + threadIdx.x * 4;
    float o0 = gg.x * dx * inv + bb.x;
    float o1 = gg.y * dy * inv + bb.y;
    float o2 = gg.z * dz * inv + bb.z;
    float o3 = gg.w * dw * inv + bb.w;
    split2(o0, xnh[base+0], xnl[base+0]);
    split2(o1, xnh[base+1], xnl[base+1]);
    split2(o2, xnh[base+2], xnl[base+2]);
    split2(o3, xnh[base+3], xnl[base+3]);
}

// ---------------- bf16x3 mma.sync GEMM ---------------------------------------
// C[M,1024] = A[M,1024] @ W[1024,1024]^T + bias, fp32 precision via
// AhiBhi + AhiBlo + AloBhi. Block tile 128x128, K-tile 32, 256 threads
// (8 warps, 4(m) x 2(n) grid, warp tile 32x64). Double-buffered cp.async.
// W[N,K] row-major IS col-major KxN, so B fragments use NON-trans ldmatrix.
// MODE 0: plain store, MODE 1: qkv scatter [B,H,S,DK], MODE 2: residual add.
#define RSTR   80                         // smem row stride in bytes (40 bf16)
#define TILE_B (128 * RSTR)               // 10240 B per tile
#define STAGE_B (4 * TILE_B)              // Ah, Al, Bh, Bl
#define GEMM_SMEM (2 * STAGE_B)           // 81920 B

template<int MODE>
__global__ void __launch_bounds__(256) gemm_bf16(
    const __nv_bfloat16* __restrict__ Ahi, const __nv_bfloat16* __restrict__ Alo,
    const __nv_bfloat16* __restrict__ Bhi, const __nv_bfloat16* __restrict__ Blo,
    const float* __restrict__ bias, const float* __restrict__ res,
    float* __restrict__ C)
{
    extern __shared__ char sm[];
    const uint32_t sbase = smem_u32(sm);
    const int tid = threadIdx.x, lane = tid & 31, wid = tid >> 5;
    const int bm = blockIdx.y * 128, bn = blockIdx.x * 128;
    const int wm = (wid & 3) * 32, wn = (wid >> 2) * 64;

    float acc[2][8][4];
    #pragma unroll
    for (int a = 0; a < 2; a++)
        #pragma unroll
        for (int b = 0; b < 8; b++)
            #pragma unroll
            for (int c = 0; c < 4; c++) acc[a][b][c] = 0.f;

    // stage loader: 4 tiles x 512 16B-chunks, 2 chunks/thread/tile
    auto load_stage = [&](int stage, int k0) {
        const uint32_t sb = sbase + stage * STAGE_B;
        const __nv_bfloat16* gsrc[4] = { Ahi, Alo, Bhi, Blo };
        const int row0[4] = { bm, bm, bn, bn };
        #pragma unroll
        for (int t = 0; t < 4; t++) {
            const __nv_bfloat16* gp = gsrc[t];
            #pragma unroll
            for (int j = 0; j < 2; j++) {
                int chunk = tid + j * 256;
                int row = chunk >> 2, cs = chunk & 3;
                const void* src = gp + (size_t)(row0[t] + row) * KP + k0 + cs * 8;
                cpa16(sb + t * TILE_B + row * RSTR + cs * 16, src);
            }
        }
    };

    load_stage(0, 0);
    CP_COMMIT();

    for (int i = 0; i < 32; i++) {
        if (i + 1 < 32) {
            load_stage((i + 1) & 1, (i + 1) * 32);
            CP_COMMIT();
            CP_WAIT(1);
        } else {
            CP_WAIT(0);
        }
        __syncthreads();

        const uint32_t sa = sbase + (i & 1) * STAGE_B;          // A hi
        const uint32_t sb = sa + 2 * TILE_B;                    // B hi
        #pragma unroll
        for (int kk = 0; kk < 32; kk += 16) {
            const uint32_t cb = (kk + ((lane >> 4) << 3)) * 2;
            uint32_t ah[2][4], al[2][4];
            #pragma unroll
            for (int am = 0; am < 2; am++) {
                uint32_t ad = sa + (wm + am * 16 + (lane & 15)) * RSTR + cb;
                LDSM4(ah[am], ad);
                LDSM4(al[am], ad + TILE_B);
            }
            #pragma unroll
            for (int g = 0; g < 4; g++) {                       // n16 groups
                uint32_t bh[4], bl[4];
                uint32_t bd = sb + (wn + g * 16 + (lane & 15)) * RSTR + cb;
                LDSM4(bh, bd);
                LDSM4(bl, bd + TILE_B);
                #pragma unroll
                for (int am = 0; am < 2; am++) {
                    MMA_BF16(acc[am][2*g],   ah[am], bh[0], bh[2]);
                    MMA_BF16(acc[am][2*g+1], ah[am], bh[1], bh[3]);
                    MMA_BF16(acc[am][2*g],   ah[am], bl[0], bl[2]);
                    MMA_BF16(acc[am][2*g+1], ah[am], bl[1], bl[3]);
                    MMA_BF16(acc[am][2*g],   al[am], bh[0], bh[2]);
                    MMA_BF16(acc[am][2*g+1], al[am], bh[1], bh[3]);
                }
            }
        }
        __syncthreads();
    }

    // epilogue: thread (am, an) pair rows (q/4, +8), cols (q%4)*2, +1
    #pragma unroll
    for (int am = 0; am < 2; am++) {
        #pragma unroll
        for (int an = 0; an < 8; an++) {
            int mrow = bm + wm + am * 16 + (lane >> 2);
            int ncol = bn + wn + an * 8 + (lane & 3) * 2;
            float b0 = bias[ncol], b1 = bias[ncol + 1];
            #pragma unroll
            for (int r = 0; r < 2; r++) {
                int m = mrow + r * 8;
                float v0 = acc[am][an][r * 2]     + b0;
                float v1 = acc[am][an][r * 2 + 1] + b1;
                if (MODE == 0) {
                    *(float2*)&C[(size_t)m * 1024 + ncol] = make_float2(v0, v1);
                } else if (MODE == 1) {
                    int bb = m >> 10, s = m & 1023, h = ncol >> 6, d = ncol & 63;
                    *(float2*)&C[(size_t)(((bb << 4) + h) * 1024 + s) * 64 + d] =
                        make_float2(v0, v1);
                } else {
                    const float2 rr = *(const float2*)&res[(size_t)m * 1024 + ncol];
                    *(float2*)&C[(size_t)m * 1024 + ncol] =
                        make_float2(rr.x + v0, rr.y + v1);
                }
            }
        }
    }
}

// ---------------- final decode -----------------------------------------------
__global__ void __launch_bounds__(512) dec_k(
    const float* __restrict__ x2, const float* __restrict__ w,
    const float* __restrict__ bias, float* __restrict__ out)
{
    const int m = blockIdx.x;
    const int b = m >> 10, s = m & 1023;
    const int n = threadIdx.x >> 5;
    const int lane = threadIdx.x & 31;
    const float4* xr = (const float4*)(x2 + (size_t)m * FDEC);
    const float4* wr = (const float4*)(w  + (size_t)n * FDEC);
    float sum = 0.f;
    #pragma unroll
    for (int i = 0; i < 8; i++) {
        float4 a  = xr[lane + i * 32];
        float4 ww = wr[lane + i * 32];
        sum += a.x * ww.x + a.y * ww.y + a.z * ww.z + a.w * ww.w;
    }
    #pragma unroll
    for (int o = 16; o; o >>= 1) sum += __shfl_xor_sync(0xffffffffu, sum, o);
    if (lane == 0)
        out[(size_t)(b * FD + n) * NS + s] = sum + bias[n];
}

// ---------------- flash-style causal attention with ALiBi --------------------
#define PAD 68
#define ATTN_SMEM (4 * 64 * PAD * (int)sizeof(float))

__global__ void __launch_bounds__(128) attn_k(
    const float* __restrict__ q, const float* __restrict__ k,
    const float* __restrict__ v,
    __nv_bfloat16* __restrict__ ohi, __nv_bfloat16* __restrict__ olo)
{
    extern __shared__ float smf[];
    float* Qs = smf;
    float* Ks = Qs + 64 * PAD;
    float* Vs = Ks + 64 * PAD;
    float* Ss = Vs + 64 * PAD;

    const int b = blockIdx.z, h = blockIdx.y, qc = blockIdx.x;
    const int tid = threadIdx.x;
    const int lrow = tid >> 1, lcol0 = (tid & 1) * 32;
    const int tx = tid & 7, ty = tid >> 3;

    const size_t head = (size_t)(b * NH + h) * NS * NDK;
    const float* qb = q + head;
    const float* kb = k + head;
    const float* vb = v + head;

    {
        const float* src = qb + (size_t)(qc * 64 + lrow) * 64 + lcol0;
        float* dst = Qs + lrow * PAD + lcol0;
        #pragma unroll
        for (int c = 0; c < 32; c += 4) {
            float4 t = *(const float4*)(src + c);
            t.x *= 0.125f; t.y *= 0.125f; t.z *= 0.125f; t.w *= 0.125f;
            *(float4*)(dst + c) = t;
        }
    }

    const float slope = exp2f(-0.5f * (float)(h + 1));
    float m_r[4], l_r[4], Oa[4][8];
    #pragma unroll
    for (int r = 0; r < 4; r++) {
        m_r[r] = -1e30f; l_r[r] = 0.f;
        #pragma unroll
        for (int c = 0; c < 8; c++) Oa[r][c] = 0.f;
    }

    const int ibase = qc * 64 + ty * 4;

    for (int kc = 0; kc <= qc; kc++) {
        {
            const float* ks = kb + (size_t)(kc * 64 + lrow) * 64 + lcol0;
            const float* vs = vb + (size_t)(kc * 64 + lrow) * 64 + lcol0;
            float* kd = Ks + lrow * PAD + lcol0;
            float* vd = Vs + lrow * PAD + lcol0;
            #pragma unroll
            for (int c = 0; c < 32; c += 4) {
                *(float4*)(kd + c) = *(const float4*)(ks + c);
                *(float4*)(vd + c) = *(const float4*)(vs + c);
            }
        }
        __syncthreads();

        float s_[4][8];
        #pragma unroll
        for (int r = 0; r < 4; r++)
            #pragma unroll
            for (int j = 0; j < 8; j++) s_[r][j] = 0.f;

        #pragma unroll
        for (int d = 0; d < 64; d += 4) {
            float qa[4][4], kv_[8][4];
            #pragma unroll
            for (int r = 0; r < 4; r++) {
                float4 t = *(const float4*)&Qs[(ty * 4 + r) * PAD + d];
                qa[r][0]=t.x; qa[r][1]=t.y; qa[r][2]=t.z; qa[r][3]=t.w;
            }
            #pragma unroll
            for (int j = 0; j < 8; j++) {
                float4 t = *(const float4*)&Ks[(tx * 8 + j) * PAD + d];
                kv_[j][0]=t.x; kv_[j][1]=t.y; kv_[j][2]=t.z; kv_[j][3]=t.w;
            }
            #pragma unroll
            for (int r = 0; r < 4; r++)
                #pragma unroll
                for (int j = 0; j < 8; j++)
                    #pragma unroll
                    for (int dd = 0; dd < 4; dd++)
                        s_[r][j] = fmaf(qa[r][dd], kv_[j][dd], s_[r][j]);
        }

        const int jbase = kc * 64 + tx * 8;
        #pragma unroll
        for (int r = 0; r < 4; r++) {
            int ig = ibase + r;
            float mx = -1e30f;
            #pragma unroll
            for (int j = 0; j < 8; j++) {
                int jg = jbase + j;
                float val = s_[r][j] + slope * (float)jg;
                if (jg > ig) val -= 1e9f;
                s_[r][j] = val;
                mx = fmaxf(mx, val);
            }
            mx = fmaxf(mx, __shfl_xor_sync(0xffffffffu, mx, 1));
            mx = fmaxf(mx, __shfl_xor_sync(0xffffffffu, mx, 2));
            mx = fmaxf(mx, __shfl_xor_sync(0xffffffffu, mx, 4));
            float mnew = fmaxf(m_r[r], mx);
            float corr = __expf(m_r[r] - mnew);
            m_r[r] = mnew;
            float rs = 0.f;
            #pragma unroll
            for (int j = 0; j < 8; j++) {
                float p = __expf(s_[r][j] - mnew);
                rs += p;
                Ss[(ty * 4 + r) * PAD + tx * 8 + j] = p;
            }
            rs += __shfl_xor_sync(0xffffffffu, rs, 1);
            rs += __shfl_xor_sync(0xffffffffu, rs, 2);
            rs += __shfl_xor_sync(0xffffffffu, rs, 4);
            l_r[r] = l_r[r] * corr + rs;
            #pragma unroll
            for (int c = 0; c < 8; c++) Oa[r][c] *= corr;
        }
        __syncthreads();

        #pragma unroll
        for (int j = 0; j < 64; j += 4) {
            float pr[4][4];
            #pragma unroll
            for (int r = 0; r < 4; r++) {
                float4 t = *(const float4*)&Ss[(ty * 4 + r) * PAD + j];
                pr[r][0]=t.x; pr[r][1]=t.y; pr[r][2]=t.z; pr[r][3]=t.w;
            }
            #pragma unroll
            for (int jj = 0; jj < 4; jj++) {
                float vv[8];
                *(float4*)(vv)     = *(const float4*)&Vs[(j + jj) * PAD + tx * 8];
                *(float4*)(vv + 4) = *(const float4*)&Vs[(j + jj) * PAD + tx * 8 + 4];
                #pragma unroll
                for (int r = 0; r < 4; r++)
                    #pragma unroll
                    for (int c = 0; c < 8; c++)
                        Oa[r][c] = fmaf(pr[r][jj], vv[c], Oa[r][c]);
            }
        }
        __syncthreads();
    }

    // write o hi/lo in [B,S,H*DK] layout
    #pragma unroll
    for (int r = 0; r < 4; r++) {
        int sg = ibase + r;
        float inv = 1.0f / l_r[r];
        size_t base = (size_t)(b * NS + sg) * (NH * NDK) + h * NDK + tx * 8;
        #pragma unroll
        for (int c = 0; c < 8; c++) {
            float val = Oa[r][c] * inv;
            split2(val, ohi[base + c], olo[base + c]);
        }
    }
}

// ---------------- launcher ----------------------------------------------------
extern "C" void kernel_launch(void* const* d_in, const int* in_sizes, int n_in,
                              void* d_out, int out_size)
{
    const float* z   = (const float*)d_in[0];
    const float* r   = (const float*)d_in[1];
    const float* dwn = (const float*)d_in[2];
    const float* dbn = (const float*)d_in[3];
    const float* lng = (const float*)d_in[4];
    const float* lnb = (const float*)d_in[5];
    const float* wq  = (const float*)d_in[6];
    const float* bq  = (const float*)d_in[7];
    const float* wk  = (const float*)d_in[8];
    const float* bk  = (const float*)d_in[9];
    const float* wv  = (const float*)d_in[10];
    const float* bv  = (const float*)d_in[11];
    const float* wo  = (const float*)d_in[12];
    const float* bo  = (const float*)d_in[13];
    const float* dcw = (const float*)d_in[14];
    const float* dcb = (const float*)d_in[15];
    float* out = (float*)d_out;

    float *x, *q, *k, *v, *x2;
    __nv_bfloat16 *xch, *xcl, *xnh, *xnl, *oh, *ol;
    __nv_bfloat16 *wdh, *wdl, *wqh, *wql, *wkh, *wkl, *wvh, *wvl, *woh, *wol;
    cudaGetSymbolAddress((void**)&x,   g_x);
    cudaGetSymbolAddress((void**)&q,   g_q);
    cudaGetSymbolAddress((void**)&k,   g_k);
    cudaGetSymbolAddress((void**)&v,   g_v);
    cudaGetSymbolAddress((void**)&x2,  g_x2);
    cudaGetSymbolAddress((void**)&xch, g_xc_h); cudaGetSymbolAddress((void**)&xcl, g_xc_l);
    cudaGetSymbolAddress((void**)&xnh, g_xn_h); cudaGetSymbolAddress((void**)&xnl, g_xn_l);
    cudaGetSymbolAddress((void**)&oh,  g_o_h);  cudaGetSymbolAddress((void**)&ol,  g_o_l);
    cudaGetSymbolAddress((void**)&wdh, g_wd_h); cudaGetSymbolAddress((void**)&wdl, g_wd_l);
    cudaGetSymbolAddress((void**)&wqh, g_wq_h); cudaGetSymbolAddress((void**)&wql, g_wq_l);
    cudaGetSymbolAddress((void**)&wkh, g_wk_h); cudaGetSymbolAddress((void**)&wkl, g_wk_l);
    cudaGetSymbolAddress((void**)&wvh, g_wv_h); cudaGetSymbolAddress((void**)&wvl, g_wv_l);
    cudaGetSymbolAddress((void**)&woh, g_wo_h); cudaGetSymbolAddress((void**)&wol, g_wo_l);

    cudaFuncSetAttribute(gemm_bf16<0>, cudaFuncAttributeMaxDynamicSharedMemorySize, GEMM_SMEM);
    cudaFuncSetAttribute(gemm_bf16<1>, cudaFuncAttributeMaxDynamicSharedMemorySize, GEMM_SMEM);
    cudaFuncSetAttribute(gemm_bf16<2>, cudaFuncAttributeMaxDynamicSharedMemorySize, GEMM_SMEM);
    cudaFuncSetAttribute(attn_k,       cudaFuncAttributeMaxDynamicSharedMemorySize, ATTN_SMEM);

    const int WELTS = FDEC * KP;
    concat_split_k<<<(MROWS * KP + 255) / 256, 256>>>(r, z, xch, xcl);
    wsplit_k<<<(WELTS + 255) / 256, 256>>>(dwn, wdh, wdl, KINR);
    wsplit_k<<<(WELTS + 255) / 256, 256>>>(wq, wqh, wql, FDEC);
    wsplit_k<<<(WELTS + 255) / 256, 256>>>(wk, wkh, wkl, FDEC);
    wsplit_k<<<(WELTS + 255) / 256, 256>>>(wv, wvh, wvl, FDEC);
    wsplit_k<<<(WELTS + 255) / 256, 256>>>(wo, woh, wol, FDEC);

    dim3 ggrid(8, 64);
    gemm_bf16<0><<<ggrid, 256, GEMM_SMEM>>>(xch, xcl, wdh, wdl, dbn, nullptr, x);
    ln_k<<<MROWS, 256>>>(x, lng, lnb, xnh, xnl);
    gemm_bf16<1><<<ggrid, 256, GEMM_SMEM>>>(xnh, xnl, wqh, wql, bq, nullptr, q);
    gemm_bf16<1><<<ggrid, 256, GEMM_SMEM>>>(xnh, xnl, wkh, wkl, bk, nullptr, k);
    gemm_bf16<1><<<ggrid, 256, GEMM_SMEM>>>(xnh, xnl, wvh, wvl, bv, nullptr, v);
    attn_k<<<dim3(NS / 64, NH, NB), 128, ATTN_SMEM>>>(q, k, v, oh, ol);
    gemm_bf16<2><<<ggrid, 256, GEMM_SMEM>>>(oh, ol, woh, wol, bo, x, x2);
    dec_k<<<MROWS, 512>>>(x2, dcw, dcb, out);
}

// round 7
// speedup vs baseline: 2.6688x; 1.8591x over previous
#include <cuda_runtime.h>
#include <cuda_bf16.h>
#include <cstdint>
#include <math.h>

// Problem dims (fixed)
#define NB   8
#define NS   1024
#define NH   16
#define NDK  64
#define FDEC 1024
#define FD   16
#define KINR 784          // real K of dense input (16 + 768)
#define KP   1024         // padded K for all GEMMs
#define MROWS (NB*NS)     // 8192

// ---------------- scratch (static __device__, no allocation) ----------------
__device__ float g_x   [MROWS * FDEC];   // dense output (residual source)
__device__ float g_q   [MROWS * FDEC];
__device__ float g_k   [MROWS * FDEC];
__device__ float g_v   [MROWS * FDEC];
__device__ float g_x2  [MROWS * FDEC];

__device__ __nv_bfloat16 g_xc_h[MROWS * KP], g_xc_l[MROWS * KP];
__device__ __nv_bfloat16 g_xn_h[MROWS * KP], g_xn_l[MROWS * KP];
__device__ __nv_bfloat16 g_o_h [MROWS * KP], g_o_l [MROWS * KP];

__device__ __nv_bfloat16 g_wd_h[FDEC * KP], g_wd_l[FDEC * KP];
__device__ __nv_bfloat16 g_wq_h[FDEC * KP], g_wq_l[FDEC * KP];
__device__ __nv_bfloat16 g_wk_h[FDEC * KP], g_wk_l[FDEC * KP];
__device__ __nv_bfloat16 g_wv_h[FDEC * KP], g_wv_l[FDEC * KP];
__device__ __nv_bfloat16 g_wo_h[FDEC * KP], g_wo_l[FDEC * KP];

// ---------------- PTX helpers (sm_80-level: mma.sync / ldmatrix / cp.async) --
__device__ __forceinline__ uint32_t smem_u32(const void* p) {
    uint32_t a;
    asm("{ .reg .u64 t; cvta.to.shared.u64 t, %1; cvt.u32.u64 %0, t; }" : "=r"(a) : "l"(p));
    return a;
}

#define LDSM4(R, A) \
    asm volatile("ldmatrix.sync.aligned.m8n8.x4.shared.b16 {%0,%1,%2,%3}, [%4];" \
        : "=r"((R)[0]), "=r"((R)[1]), "=r"((R)[2]), "=r"((R)[3]) : "r"(A))

#define MMA_BF16(C, A, B0, B1) \
    asm volatile("mma.sync.aligned.m16n8k16.row.col.f32.bf16.bf16.f32 " \
        "{%0,%1,%2,%3},{%4,%5,%6,%7},{%8,%9},{%0,%1,%2,%3};" \
        : "+f"((C)[0]), "+f"((C)[1]), "+f"((C)[2]), "+f"((C)[3]) \
        : "r"((A)[0]), "r"((A)[1]), "r"((A)[2]), "r"((A)[3]), "r"(B0), "r"(B1))

#define MMA_TF32(C, A, B0, B1) \
    asm volatile("mma.sync.aligned.m16n8k8.row.col.f32.tf32.tf32.f32 " \
        "{%0,%1,%2,%3},{%4,%5,%6,%7},{%8,%9},{%0,%1,%2,%3};" \
        : "+f"((C)[0]), "+f"((C)[1]), "+f"((C)[2]), "+f"((C)[3]) \
        : "r"((A)[0]), "r"((A)[1]), "r"((A)[2]), "r"((A)[3]), "r"(B0), "r"(B1))

__device__ __forceinline__ uint32_t to_tf32(float f) {
    uint32_t r;
    asm("cvt.rna.tf32.f32 %0, %1;" : "=r"(r) : "f"(f));
    return r;
}

__device__ __forceinline__ void cpa16(uint32_t dst, const void* src) {
    asm volatile("cp.async.cg.shared.global [%0], [%1], 16;" :: "r"(dst), "l"(src));
}
#define CP_COMMIT() asm volatile("cp.async.commit_group;" ::: "memory")
#define CP_WAIT(n)  asm volatile("cp.async.wait_group %0;" :: "n"(n) : "memory")

// ---------------- fp32 -> (hi, lo) bf16 split --------------------------------
__device__ __forceinline__ void split2(float v, __nv_bfloat16& h, __nv_bfloat16& l) {
    h = __float2bfloat16(v);
    l = __float2bfloat16(v - __bfloat162float(h));
}

// concat(r_traj, z, pad) -> xc hi/lo [8192, 1024]
__global__ void __launch_bounds__(256) concat_split_k(
    const float* __restrict__ r, const float* __restrict__ z,
    __nv_bfloat16* __restrict__ hi, __nv_bfloat16* __restrict__ lo)
{
    int idx = blockIdx.x * 256 + threadIdx.x;
    if (idx >= MROWS * KP) return;
    int m = idx >> 10, f = idx & 1023;
    float v = (f < 16) ? r[m * 16 + f]
            : (f < KINR) ? z[(m >> 10) * 768 + (f - 16)] : 0.f;
    split2(v, hi[idx], lo[idx]);
}

// weight split with K padding: w [1024, Ksrc] -> hi/lo [1024, 1024]
__global__ void __launch_bounds__(256) wsplit_k(
    const float* __restrict__ w, __nv_bfloat16* __restrict__ hi,
    __nv_bfloat16* __restrict__ lo, int Ksrc)
{
    int idx = blockIdx.x * 256 + threadIdx.x;
    if (idx >= FDEC * KP) return;
    int n = idx >> 10, k = idx & 1023;
    float v = (k < Ksrc) ? w[n * Ksrc + k] : 0.f;
    split2(v, hi[idx], lo[idx]);
}

// ---------------- LayerNorm (fp32 in, bf16 hi/lo out) ------------------------
__device__ __forceinline__ float blockReduce(float val, float* sh)
{
    __syncthreads();
    int lane = threadIdx.x & 31, wid = threadIdx.x >> 5;
    #pragma unroll
    for (int o = 16; o; o >>= 1) val += __shfl_xor_sync(0xffffffffu, val, o);
    if (lane == 0) sh[wid] = val;
    __syncthreads();
    if (wid == 0) {
        val = (lane < 8) ? sh[lane] : 0.f;
        #pragma unroll
        for (int o = 4; o; o >>= 1) val += __shfl_xor_sync(0xffffffffu, val, o);
        if (lane == 0) sh[0] = val;
    }
    __syncthreads();
    return sh[0];
}

__global__ void __launch_bounds__(256) ln_k(
    const float* __restrict__ x, const float* __restrict__ g,
    const float* __restrict__ beta,
    __nv_bfloat16* __restrict__ xnh, __nv_bfloat16* __restrict__ xnl)
{
    __shared__ float red[32];
    int row = blockIdx.x;
    float4 v = ((const float4*)(x + (size_t)row * 1024))[threadIdx.x];
    float s = blockReduce(v.x + v.y + v.z + v.w, red);
    float mean = s * (1.0f / 1024.0f);
    float dx = v.x - mean, dy = v.y - mean, dz = v.z - mean, dw = v.w - mean;
    float s2 = blockReduce(dx*dx + dy*dy + dz*dz + dw*dw, red);
    float inv = rsqrtf(s2 * (1.0f / 1024.0f) + 1e-6f);
    float4 gg = ((const float4*)g)[threadIdx.x];
    float4 bb = ((const float4*)beta)[threadIdx.x];
    size_t base = (size_t)row * 1024 + threadIdx.x * 4;
    float o0 = gg.x * dx * inv + bb.x;
    float o1 = gg.y * dy * inv + bb.y;
    float o2 = gg.z * dz * inv + bb.z;
    float o3 = gg.w * dw * inv + bb.w;
    split2(o0, xnh[base+0], xnl[base+0]);
    split2(o1, xnh[base+1], xnl[base+1]);
    split2(o2, xnh[base+2], xnl[base+2]);
    split2(o3, xnh[base+3], xnl[base+3]);
}

// ---------------- bf16x3 mma.sync GEMM ---------------------------------------
#define RSTR   80
#define TILE_B (128 * RSTR)
#define STAGE_B (4 * TILE_B)
#define GEMM_SMEM (2 * STAGE_B)

template<int MODE>
__global__ void __launch_bounds__(256) gemm_bf16(
    const __nv_bfloat16* __restrict__ Ahi, const __nv_bfloat16* __restrict__ Alo,
    const __nv_bfloat16* __restrict__ Bhi, const __nv_bfloat16* __restrict__ Blo,
    const float* __restrict__ bias, const float* __restrict__ res,
    float* __restrict__ C)
{
    extern __shared__ char sm[];
    const uint32_t sbase = smem_u32(sm);
    const int tid = threadIdx.x, lane = tid & 31, wid = tid >> 5;
    const int bm = blockIdx.y * 128, bn = blockIdx.x * 128;
    const int wm = (wid & 3) * 32, wn = (wid >> 2) * 64;

    float acc[2][8][4];
    #pragma unroll
    for (int a = 0; a < 2; a++)
        #pragma unroll
        for (int b = 0; b < 8; b++)
            #pragma unroll
            for (int c = 0; c < 4; c++) acc[a][b][c] = 0.f;

    auto load_stage = [&](int stage, int k0) {
        const uint32_t sb = sbase + stage * STAGE_B;
        const __nv_bfloat16* gsrc[4] = { Ahi, Alo, Bhi, Blo };
        const int row0[4] = { bm, bm, bn, bn };
        #pragma unroll
        for (int t = 0; t < 4; t++) {
            const __nv_bfloat16* gp = gsrc[t];
            #pragma unroll
            for (int j = 0; j < 2; j++) {
                int chunk = tid + j * 256;
                int row = chunk >> 2, cs = chunk & 3;
                const void* src = gp + (size_t)(row0[t] + row) * KP + k0 + cs * 8;
                cpa16(sb + t * TILE_B + row * RSTR + cs * 16, src);
            }
        }
    };

    load_stage(0, 0);
    CP_COMMIT();

    for (int i = 0; i < 32; i++) {
        if (i + 1 < 32) {
            load_stage((i + 1) & 1, (i + 1) * 32);
            CP_COMMIT();
            CP_WAIT(1);
        } else {
            CP_WAIT(0);
        }
        __syncthreads();

        const uint32_t sa = sbase + (i & 1) * STAGE_B;
        const uint32_t sb = sa + 2 * TILE_B;
        #pragma unroll
        for (int kk = 0; kk < 32; kk += 16) {
            const uint32_t cb = (kk + ((lane >> 4) << 3)) * 2;
            uint32_t ah[2][4], al[2][4];
            #pragma unroll
            for (int am = 0; am < 2; am++) {
                uint32_t ad = sa + (wm + am * 16 + (lane & 15)) * RSTR + cb;
                LDSM4(ah[am], ad);
                LDSM4(al[am], ad + TILE_B);
            }
            #pragma unroll
            for (int g = 0; g < 4; g++) {
                uint32_t bh[4], bl[4];
                uint32_t bd = sb + (wn + g * 16 + (lane & 15)) * RSTR + cb;
                LDSM4(bh, bd);
                LDSM4(bl, bd + TILE_B);
                #pragma unroll
                for (int am = 0; am < 2; am++) {
                    MMA_BF16(acc[am][2*g],   ah[am], bh[0], bh[2]);
                    MMA_BF16(acc[am][2*g+1], ah[am], bh[1], bh[3]);
                    MMA_BF16(acc[am][2*g],   ah[am], bl[0], bl[2]);
                    MMA_BF16(acc[am][2*g+1], ah[am], bl[1], bl[3]);
                    MMA_BF16(acc[am][2*g],   al[am], bh[0], bh[2]);
                    MMA_BF16(acc[am][2*g+1], al[am], bh[1], bh[3]);
                }
            }
        }
        __syncthreads();
    }

    #pragma unroll
    for (int am = 0; am < 2; am++) {
        #pragma unroll
        for (int an = 0; an < 8; an++) {
            int mrow = bm + wm + am * 16 + (lane >> 2);
            int ncol = bn + wn + an * 8 + (lane & 3) * 2;
            float b0 = bias[ncol], b1 = bias[ncol + 1];
            #pragma unroll
            for (int r = 0; r < 2; r++) {
                int m = mrow + r * 8;
                float v0 = acc[am][an][r * 2]     + b0;
                float v1 = acc[am][an][r * 2 + 1] + b1;
                if (MODE == 0) {
                    *(float2*)&C[(size_t)m * 1024 + ncol] = make_float2(v0, v1);
                } else if (MODE == 1) {
                    int bb = m >> 10, s = m & 1023, h = ncol >> 6, d = ncol & 63;
                    *(float2*)&C[(size_t)(((bb << 4) + h) * 1024 + s) * 64 + d] =
                        make_float2(v0, v1);
                } else {
                    const float2 rr = *(const float2*)&res[(size_t)m * 1024 + ncol];
                    *(float2*)&C[(size_t)m * 1024 + ncol] =
                        make_float2(rr.x + v0, rr.y + v1);
                }
            }
        }
    }
}

// ---------------- final decode -----------------------------------------------
__global__ void __launch_bounds__(512) dec_k(
    const float* __restrict__ x2, const float* __restrict__ w,
    const float* __restrict__ bias, float* __restrict__ out)
{
    const int m = blockIdx.x;
    const int b = m >> 10, s = m & 1023;
    const int n = threadIdx.x >> 5;
    const int lane = threadIdx.x & 31;
    const float4* xr = (const float4*)(x2 + (size_t)m * FDEC);
    const float4* wr = (const float4*)(w  + (size_t)n * FDEC);
    float sum = 0.f;
    #pragma unroll
    for (int i = 0; i < 8; i++) {
        float4 a  = xr[lane + i * 32];
        float4 ww = wr[lane + i * 32];
        sum += a.x * ww.x + a.y * ww.y + a.z * ww.z + a.w * ww.w;
    }
    #pragma unroll
    for (int o = 16; o; o >>= 1) sum += __shfl_xor_sync(0xffffffffu, sum, o);
    if (lane == 0)
        out[(size_t)(b * FD + n) * NS + s] = sum + bias[n];
}

// ---------------- tf32 mma flash attention with ALiBi ------------------------
// CTA = 64 q rows of one (b,h); 4 warps x 16 rows; KV tiles of 64.
// K in smem as [j][d] stride 68; V transposed [d][j] stride 68; P roundtrip
// through smem for A-fragment reload. Causal additive -1e9 matches reference.
#define ASTR 68
#define ATTN_SMEM (3 * 64 * ASTR * (int)sizeof(float))

__global__ void __launch_bounds__(128) attn_tc(
    const float* __restrict__ q, const float* __restrict__ k,
    const float* __restrict__ v,
    __nv_bfloat16* __restrict__ ohi, __nv_bfloat16* __restrict__ olo)
{
    extern __shared__ float smf[];
    float* Ks = smf;                 // [64][68]  K[j][d]
    float* Vs = Ks + 64 * ASTR;      // [64][68]  V^T: Vs[d][j]
    float* Ps = Vs + 64 * ASTR;      // [64][68]  P[row][j]

    const int qc = blockIdx.x, h = blockIdx.y, b = blockIdx.z;
    const int tid = threadIdx.x, lane = tid & 31, w = tid >> 5;
    const int g4 = lane >> 2, t4 = lane & 3;     // groupID, thread-in-group

    const size_t head = (size_t)(b * NH + h) * NS * NDK;
    const float* qb = q + head;
    const float* kb = k + head;
    const float* vb = v + head;

    // Q a-fragments (tf32, pre-scaled), rows w*16 + g4 (+8), cols kk*8 + t4 (+4)
    uint32_t qa[8][4];
    {
        const int r0 = qc * 64 + w * 16 + g4;
        #pragma unroll
        for (int kk = 0; kk < 8; kk++) {
            int c0 = kk * 8 + t4;
            qa[kk][0] = to_tf32(qb[(size_t)r0 * 64 + c0] * 0.125f);
            qa[kk][1] = to_tf32(qb[(size_t)(r0 + 8) * 64 + c0] * 0.125f);
            qa[kk][2] = to_tf32(qb[(size_t)r0 * 64 + c0 + 4] * 0.125f);
            qa[kk][3] = to_tf32(qb[(size_t)(r0 + 8) * 64 + c0 + 4] * 0.125f);
        }
    }

    const float slope = exp2f(-0.5f * (float)(h + 1));
    float oacc[8][4];
    #pragma unroll
    for (int dt = 0; dt < 8; dt++)
        #pragma unroll
        for (int c = 0; c < 4; c++) oacc[dt][c] = 0.f;
    float mrow[2] = { -1e30f, -1e30f };
    float lrow[2] = { 0.f, 0.f };

    const int lrow_ld = tid >> 1, lcol0 = (tid & 1) * 32;   // tile loads

    for (int kc = 0; kc <= qc; kc++) {
        // load K [j][d] and V transposed [d][j]
        {
            const float* ksrc = kb + (size_t)(kc * 64 + lrow_ld) * 64 + lcol0;
            const float* vsrc = vb + (size_t)(kc * 64 + lrow_ld) * 64 + lcol0;
            float* kd = Ks + lrow_ld * ASTR + lcol0;
            #pragma unroll
            for (int c = 0; c < 32; c += 4) {
                float4 t = *(const float4*)(ksrc + c);
                *(float4*)(kd + c) = t;
                float4 tv = *(const float4*)(vsrc + c);
                Vs[(lcol0 + c + 0) * ASTR + lrow_ld] = tv.x;
                Vs[(lcol0 + c + 1) * ASTR + lrow_ld] = tv.y;
                Vs[(lcol0 + c + 2) * ASTR + lrow_ld] = tv.z;
                Vs[(lcol0 + c + 3) * ASTR + lrow_ld] = tv.w;
            }
        }
        __syncthreads();

        // S = Q K^T  (8 n-tiles of 8 cols)
        float sc[8][4];
        #pragma unroll
        for (int nt = 0; nt < 8; nt++) {
            sc[nt][0] = sc[nt][1] = sc[nt][2] = sc[nt][3] = 0.f;
            #pragma unroll
            for (int kk = 0; kk < 8; kk++) {
                const float* kp = &Ks[(nt * 8 + g4) * ASTR + kk * 8 + t4];
                uint32_t b0 = to_tf32(kp[0]);
                uint32_t b1 = to_tf32(kp[4]);
                MMA_TF32(sc[nt], qa[kk], b0, b1);
            }
        }

        // softmax (rows g4 and g4+8 of this warp's 16)
        const bool diag = (kc == qc);
        #pragma unroll
        for (int half = 0; half < 2; half++) {
            const int wr = w * 16 + g4 + half * 8;       // block-local row
            const int ig = qc * 64 + wr;
            float mx = -1e30f;
            #pragma unroll
            for (int nt = 0; nt < 8; nt++) {
                #pragma unroll
                for (int e = 0; e < 2; e++) {
                    int jl = nt * 8 + t4 * 2 + e;
                    int jg = kc * 64 + jl;
                    float val = sc[nt][half * 2 + e] + slope * (float)jg;
                    if (diag && jg > ig) val -= 1e9f;
                    sc[nt][half * 2 + e] = val;
                    mx = fmaxf(mx, val);
                }
            }
            mx = fmaxf(mx, __shfl_xor_sync(0xffffffffu, mx, 1));
            mx = fmaxf(mx, __shfl_xor_sync(0xffffffffu, mx, 2));
            float mnew = fmaxf(mrow[half], mx);
            float corr = __expf(mrow[half] - mnew);
            mrow[half] = mnew;
            float rs = 0.f;
            #pragma unroll
            for (int nt = 0; nt < 8; nt++) {
                #pragma unroll
                for (int e = 0; e < 2; e++) {
                    float p = __expf(sc[nt][half * 2 + e] - mnew);
                    rs += p;
                    Ps[wr * ASTR + nt * 8 + t4 * 2 + e] = p;
                }
            }
            rs += __shfl_xor_sync(0xffffffffu, rs, 1);
            rs += __shfl_xor_sync(0xffffffffu, rs, 2);
            lrow[half] = lrow[half] * corr + rs;
            #pragma unroll
            for (int dt = 0; dt < 8; dt++) {
                oacc[dt][half * 2]     *= corr;
                oacc[dt][half * 2 + 1] *= corr;
            }
        }
        __syncwarp();

        // O += P V  (A = P from smem, B = Vs[d][j])
        #pragma unroll
        for (int kk = 0; kk < 8; kk++) {
            uint32_t pa[4];
            const int pr = w * 16 + g4;
            pa[0] = to_tf32(Ps[pr * ASTR + kk * 8 + t4]);
            pa[1] = to_tf32(Ps[(pr + 8) * ASTR + kk * 8 + t4]);
            pa[2] = to_tf32(Ps[pr * ASTR + kk * 8 + t4 + 4]);
            pa[3] = to_tf32(Ps[(pr + 8) * ASTR + kk * 8 + t4 + 4]);
            #pragma unroll
            for (int dt = 0; dt < 8; dt++) {
                const float* vp = &Vs[(dt * 8 + g4) * ASTR + kk * 8 + t4];
                uint32_t b0 = to_tf32(vp[0]);
                uint32_t b1 = to_tf32(vp[4]);
                MMA_TF32(oacc[dt], pa, b0, b1);
            }
        }
        __syncthreads();
    }

    // epilogue: write hi/lo bf16 pairs to [B,S,H*DK]
    #pragma unroll
    for (int half = 0; half < 2; half++) {
        const int sg = qc * 64 + w * 16 + g4 + half * 8;
        const float inv = 1.0f / lrow[half];
        const size_t base = (size_t)(b * NS + sg) * (NH * NDK) + h * NDK;
        #pragma unroll
        for (int dt = 0; dt < 8; dt++) {
            int d = dt * 8 + t4 * 2;
            float v0 = oacc[dt][half * 2]     * inv;
            float v1 = oacc[dt][half * 2 + 1] * inv;
            split2(v0, ohi[base + d],     olo[base + d]);
            split2(v1, ohi[base + d + 1], olo[base + d + 1]);
        }
    }
}

// ---------------- launcher ----------------------------------------------------
extern "C" void kernel_launch(void* const* d_in, const int* in_sizes, int n_in,
                              void* d_out, int out_size)
{
    const float* z   = (const float*)d_in[0];
    const float* r   = (const float*)d_in[1];
    const float* dwn = (const float*)d_in[2];
    const float* dbn = (const float*)d_in[3];
    const float* lng = (const float*)d_in[4];
    const float* lnb = (const float*)d_in[5];
    const float* wq  = (const float*)d_in[6];
    const float* bq  = (const float*)d_in[7];
    const float* wk  = (const float*)d_in[8];
    const float* bk  = (const float*)d_in[9];
    const float* wv  = (const float*)d_in[10];
    const float* bv  = (const float*)d_in[11];
    const float* wo  = (const float*)d_in[12];
    const float* bo  = (const float*)d_in[13];
    const float* dcw = (const float*)d_in[14];
    const float* dcb = (const float*)d_in[15];
    float* out = (float*)d_out;

    float *x, *q, *k, *v, *x2;
    __nv_bfloat16 *xch, *xcl, *xnh, *xnl, *oh, *ol;
    __nv_bfloat16 *wdh, *wdl, *wqh, *wql, *wkh, *wkl, *wvh, *wvl, *woh, *wol;
    cudaGetSymbolAddress((void**)&x,   g_x);
    cudaGetSymbolAddress((void**)&q,   g_q);
    cudaGetSymbolAddress((void**)&k,   g_k);
    cudaGetSymbolAddress((void**)&v,   g_v);
    cudaGetSymbolAddress((void**)&x2,  g_x2);
    cudaGetSymbolAddress((void**)&xch, g_xc_h); cudaGetSymbolAddress((void**)&xcl, g_xc_l);
    cudaGetSymbolAddress((void**)&xnh, g_xn_h); cudaGetSymbolAddress((void**)&xnl, g_xn_l);
    cudaGetSymbolAddress((void**)&oh,  g_o_h);  cudaGetSymbolAddress((void**)&ol,  g_o_l);
    cudaGetSymbolAddress((void**)&wdh, g_wd_h); cudaGetSymbolAddress((void**)&wdl, g_wd_l);
    cudaGetSymbolAddress((void**)&wqh, g_wq_h); cudaGetSymbolAddress((void**)&wql, g_wq_l);
    cudaGetSymbolAddress((void**)&wkh, g_wk_h); cudaGetSymbolAddress((void**)&wkl, g_wk_l);
    cudaGetSymbolAddress((void**)&wvh, g_wv_h); cudaGetSymbolAddress((void**)&wvl, g_wv_l);
    cudaGetSymbolAddress((void**)&woh, g_wo_h); cudaGetSymbolAddress((void**)&wol, g_wo_l);

    cudaFuncSetAttribute(gemm_bf16<0>, cudaFuncAttributeMaxDynamicSharedMemorySize, GEMM_SMEM);
    cudaFuncSetAttribute(gemm_bf16<1>, cudaFuncAttributeMaxDynamicSharedMemorySize, GEMM_SMEM);
    cudaFuncSetAttribute(gemm_bf16<2>, cudaFuncAttributeMaxDynamicSharedMemorySize, GEMM_SMEM);
    cudaFuncSetAttribute(attn_tc,      cudaFuncAttributeMaxDynamicSharedMemorySize, ATTN_SMEM);

    const int WELTS = FDEC * KP;
    concat_split_k<<<(MROWS * KP + 255) / 256, 256>>>(r, z, xch, xcl);
    wsplit_k<<<(WELTS + 255) / 256, 256>>>(dwn, wdh, wdl, KINR);
    wsplit_k<<<(WELTS + 255) / 256, 256>>>(wq, wqh, wql, FDEC);
    wsplit_k<<<(WELTS + 255) / 256, 256>>>(wk, wkh, wkl, FDEC);
    wsplit_k<<<(WELTS + 255) / 256, 256>>>(wv, wvh, wvl, FDEC);
    wsplit_k<<<(WELTS + 255) / 256, 256>>>(wo, woh, wol, FDEC);

    dim3 ggrid(8, 64);
    gemm_bf16<0><<<ggrid, 256, GEMM_SMEM>>>(xch, xcl, wdh, wdl, dbn, nullptr, x);
    ln_k<<<MROWS, 256>>>(x, lng, lnb, xnh, xnl);
    gemm_bf16<1><<<ggrid, 256, GEMM_SMEM>>>(xnh, xnl, wqh, wql, bq, nullptr, q);
    gemm_bf16<1><<<ggrid, 256, GEMM_SMEM>>>(xnh, xnl, wkh, wkl, bk, nullptr, k);
    gemm_bf16<1><<<ggrid, 256, GEMM_SMEM>>>(xnh, xnl, wvh, wvl, bv, nullptr, v);
    attn_tc<<<dim3(NS / 64, NH, NB), 128, ATTN_SMEM>>>(q, k, v, oh, ol);
    gemm_bf16<2><<<ggrid, 256, GEMM_SMEM>>>(oh, ol, woh, wol, bo, x, x2);
    dec_k<<<MROWS, 512>>>(x2, dcw, dcb, out);
}

// round 8
// speedup vs baseline: 3.4683x; 1.2996x over previous
#include <cuda_runtime.h>
#include <cuda_bf16.h>
#include <cstdint>
#include <math.h>

// Problem dims (fixed)
#define NB   8
#define NS   1024
#define NH   16
#define NDK  64
#define FDEC 1024
#define FD   16
#define KINR 784          // real K of dense input (16 + 768)
#define KP   1024         // padded K for all GEMMs
#define MROWS (NB*NS)     // 8192

// ---------------- scratch (static __device__, no allocation) ----------------
__device__ float g_xcat[MROWS * KP];     // concat input, fp32, K padded
__device__ float g_x   [MROWS * FDEC];   // dense output (residual source)
__device__ float g_xn  [MROWS * FDEC];   // LN output
__device__ float g_q   [MROWS * FDEC];
__device__ float g_k   [MROWS * FDEC];
__device__ float g_v   [MROWS * FDEC];
__device__ float g_o   [MROWS * FDEC];   // attention output
__device__ float g_x2  [MROWS * FDEC];
__device__ float g_wpad[FDEC * KP];      // dense weight padded 784->1024

// ---------------- PTX helpers ------------------------------------------------
__device__ __forceinline__ uint32_t smem_u32(const void* p) {
    uint32_t a;
    asm("{ .reg .u64 t; cvta.to.shared.u64 t, %1; cvt.u32.u64 %0, t; }" : "=r"(a) : "l"(p));
    return a;
}

#define MMA_TF32(C, A, B0, B1) \
    asm volatile("mma.sync.aligned.m16n8k8.row.col.f32.tf32.tf32.f32 " \
        "{%0,%1,%2,%3},{%4,%5,%6,%7},{%8,%9},{%0,%1,%2,%3};" \
        : "+f"((C)[0]), "+f"((C)[1]), "+f"((C)[2]), "+f"((C)[3]) \
        : "r"((A)[0]), "r"((A)[1]), "r"((A)[2]), "r"((A)[3]), "r"(B0), "r"(B1))

__device__ __forceinline__ uint32_t to_tf32(float f) {
    uint32_t r;
    asm("cvt.rna.tf32.f32 %0, %1;" : "=r"(r) : "f"(f));
    return r;
}

__device__ __forceinline__ void cpa16(uint32_t dst, const void* src) {
    asm volatile("cp.async.cg.shared.global [%0], [%1], 16;" :: "r"(dst), "l"(src));
}
#define CP_COMMIT() asm volatile("cp.async.commit_group;" ::: "memory")
#define CP_WAIT(n)  asm volatile("cp.async.wait_group %0;" :: "n"(n) : "memory")

// ---------------- concat(r_traj, z, pad) -> fp32 [8192, 1024] ----------------
__global__ void __launch_bounds__(256) concat_k(
    const float* __restrict__ r, const float* __restrict__ z,
    float* __restrict__ xcat)
{
    int idx = blockIdx.x * 256 + threadIdx.x;
    if (idx >= MROWS * KP) return;
    int m = idx >> 10, f = idx & 1023;
    xcat[idx] = (f < 16) ? r[m * 16 + f]
              : (f < KINR) ? z[(m >> 10) * 768 + (f - 16)] : 0.f;
}

// dense weight [1024, 784] -> padded [1024, 1024]
__global__ void __launch_bounds__(256) wpad_k(
    const float* __restrict__ w, float* __restrict__ wp)
{
    int idx = blockIdx.x * 256 + threadIdx.x;
    if (idx >= FDEC * KP) return;
    int n = idx >> 10, k = idx & 1023;
    wp[idx] = (k < KINR) ? w[n * KINR + k] : 0.f;
}

// ---------------- LayerNorm (fp32 -> fp32) -----------------------------------
__device__ __forceinline__ float blockReduce(float val, float* sh)
{
    __syncthreads();
    int lane = threadIdx.x & 31, wid = threadIdx.x >> 5;
    #pragma unroll
    for (int o = 16; o; o >>= 1) val += __shfl_xor_sync(0xffffffffu, val, o);
    if (lane == 0) sh[wid] = val;
    __syncthreads();
    if (wid == 0) {
        val = (lane < 8) ? sh[lane] : 0.f;
        #pragma unroll
        for (int o = 4; o; o >>= 1) val += __shfl_xor_sync(0xffffffffu, val, o);
        if (lane == 0) sh[0] = val;
    }
    __syncthreads();
    return sh[0];
}

__global__ void __launch_bounds__(256) ln_k(
    const float* __restrict__ x, const float* __restrict__ g,
    const float* __restrict__ beta, float* __restrict__ xn)
{
    __shared__ float red[32];
    int row = blockIdx.x;
    float4 v = ((const float4*)(x + (size_t)row * 1024))[threadIdx.x];
    float s = blockReduce(v.x + v.y + v.z + v.w, red);
    float mean = s * (1.0f / 1024.0f);
    float dx = v.x - mean, dy = v.y - mean, dz = v.z - mean, dw = v.w - mean;
    float s2 = blockReduce(dx*dx + dy*dy + dz*dz + dw*dw, red);
    float inv = rsqrtf(s2 * (1.0f / 1024.0f) + 1e-6f);
    float4 gg = ((const float4*)g)[threadIdx.x];
    float4 bb = ((const float4*)beta)[threadIdx.x];
    float4 o;
    o.x = gg.x * dx * inv + bb.x;
    o.y = gg.y * dy * inv + bb.y;
    o.z = gg.z * dz * inv + bb.z;
    o.w = gg.w * dw * inv + bb.w;
    ((float4*)(xn + (size_t)row * 1024))[threadIdx.x] = o;
}

// ---------------- tf32 mma GEMM ----------------------------------------------
// C[M,1024] = A[M,1024] @ W[1024,1024]^T + bias. Single tf32 pass.
// Block tile 128x128, K-tile 32, 256 threads (8 warps, 4(m) x 2(n)),
// warp tile 32x64. 3-stage cp.async pipeline, 1 syncthreads per k-iter.
// MODE 0: plain store, MODE 1: qkv scatter [B,H,S,DK], MODE 2: residual add.
#define GSTR  36                          // smem row stride, floats
#define TILE_BYTES (128 * GSTR * 4)       // 18432
#define STAGE_B (2 * TILE_BYTES)          // A + B tile = 36864
#define GEMM_SMEM (3 * STAGE_B)           // 110592

template<int MODE>
__global__ void __launch_bounds__(256) gemm_tf32(
    const float* __restrict__ A, const float* __restrict__ Bw,
    const float* __restrict__ bias, const float* __restrict__ res,
    float* __restrict__ C)
{
    extern __shared__ char sm[];
    const uint32_t sbase = smem_u32(sm);
    const int tid = threadIdx.x, lane = tid & 31, wid = tid >> 5;
    const int g4 = lane >> 2, t4 = lane & 3;
    const int bm = blockIdx.y * 128, bn = blockIdx.x * 128;
    const int wm = (wid & 3) * 32, wn = (wid >> 2) * 64;

    float acc[2][8][4];
    #pragma unroll
    for (int a = 0; a < 2; a++)
        #pragma unroll
        for (int b = 0; b < 8; b++)
            #pragma unroll
            for (int c = 0; c < 4; c++) acc[a][b][c] = 0.f;

    // loader: A tile 128x32 + B tile 128x32, 1024 chunks of 16B each, 4/thread
    auto load_stage = [&](int slot, int k0) {
        const uint32_t sa = sbase + slot * STAGE_B;
        #pragma unroll
        for (int c = 0; c < 4; c++) {
            int chunk = tid + c * 256;
            int row = chunk >> 3, seg = chunk & 7;
            cpa16(sa + row * (GSTR*4) + seg * 16,
                  A + (size_t)(bm + row) * KP + k0 + seg * 4);
        }
        const uint32_t sb = sa + TILE_BYTES;
        #pragma unroll
        for (int c = 0; c < 4; c++) {
            int chunk = tid + c * 256;
            int row = chunk >> 3, seg = chunk & 7;
            cpa16(sb + row * (GSTR*4) + seg * 16,
                  Bw + (size_t)(bn + row) * KP + k0 + seg * 4);
        }
    };

    load_stage(0, 0);  CP_COMMIT();
    load_stage(1, 32); CP_COMMIT();

    for (int i = 0; i < 32; i++) {
        if (i < 31) { CP_WAIT(1); } else { CP_WAIT(0); }
        __syncthreads();
        if (i + 2 < 32) { load_stage((i + 2) % 3, (i + 2) * 32); CP_COMMIT(); }

        const float* As = (const float*)(sm + (i % 3) * STAGE_B);
        const float* Bs = (const float*)(sm + (i % 3) * STAGE_B + TILE_BYTES);
        #pragma unroll
        for (int kk = 0; kk < 4; kk++) {
            uint32_t a[2][4];
            #pragma unroll
            for (int am = 0; am < 2; am++) {
                const float* ap = As + (wm + am * 16 + g4) * GSTR + kk * 8 + t4;
                a[am][0] = to_tf32(ap[0]);
                a[am][1] = to_tf32(ap[8 * GSTR]);
                a[am][2] = to_tf32(ap[4]);
                a[am][3] = to_tf32(ap[8 * GSTR + 4]);
            }
            #pragma unroll
            for (int nt = 0; nt < 8; nt++) {
                const float* bp = Bs + (wn + nt * 8 + g4) * GSTR + kk * 8 + t4;
                uint32_t b0 = to_tf32(bp[0]);
                uint32_t b1 = to_tf32(bp[4]);
                MMA_TF32(acc[0][nt], a[0], b0, b1);
                MMA_TF32(acc[1][nt], a[1], b0, b1);
            }
        }
    }

    // epilogue: acc[am][nt]: m = bm+wm+am*16+g4 (+8), n = bn+wn+nt*8+t4*2 (+1)
    #pragma unroll
    for (int am = 0; am < 2; am++) {
        #pragma unroll
        for (int nt = 0; nt < 8; nt++) {
            int mrow = bm + wm + am * 16 + g4;
            int ncol = bn + wn + nt * 8 + t4 * 2;
            float b0 = bias[ncol], b1 = bias[ncol + 1];
            #pragma unroll
            for (int r = 0; r < 2; r++) {
                int m = mrow + r * 8;
                float v0 = acc[am][nt][r * 2]     + b0;
                float v1 = acc[am][nt][r * 2 + 1] + b1;
                if (MODE == 0) {
                    *(float2*)&C[(size_t)m * 1024 + ncol] = make_float2(v0, v1);
                } else if (MODE == 1) {
                    int bb = m >> 10, s = m & 1023, h = ncol >> 6, d = ncol & 63;
                    *(float2*)&C[(size_t)(((bb << 4) + h) * 1024 + s) * 64 + d] =
                        make_float2(v0, v1);
                } else {
                    const float2 rr = *(const float2*)&res[(size_t)m * 1024 + ncol];
                    *(float2*)&C[(size_t)m * 1024 + ncol] =
                        make_float2(rr.x + v0, rr.y + v1);
                }
            }
        }
    }
}

// ---------------- final decode -----------------------------------------------
__global__ void __launch_bounds__(512) dec_k(
    const float* __restrict__ x2, const float* __restrict__ w,
    const float* __restrict__ bias, float* __restrict__ out)
{
    const int m = blockIdx.x;
    const int b = m >> 10, s = m & 1023;
    const int n = threadIdx.x >> 5;
    const int lane = threadIdx.x & 31;
    const float4* xr = (const float4*)(x2 + (size_t)m * FDEC);
    const float4* wr = (const float4*)(w  + (size_t)n * FDEC);
    float sum = 0.f;
    #pragma unroll
    for (int i = 0; i < 8; i++) {
        float4 a  = xr[lane + i * 32];
        float4 ww = wr[lane + i * 32];
        sum += a.x * ww.x + a.y * ww.y + a.z * ww.z + a.w * ww.w;
    }
    #pragma unroll
    for (int o = 16; o; o >>= 1) sum += __shfl_xor_sync(0xffffffffu, sum, o);
    if (lane == 0)
        out[(size_t)(b * FD + n) * NS + s] = sum + bias[n];
}

// ---------------- tf32 mma flash attention with ALiBi ------------------------
#define ASTR 68
#define ATTN_SMEM (3 * 64 * ASTR * (int)sizeof(float))

__global__ void __launch_bounds__(128) attn_tc(
    const float* __restrict__ q, const float* __restrict__ k,
    const float* __restrict__ v, float* __restrict__ o)
{
    extern __shared__ float smf[];
    float* Ks = smf;                 // [64][68]  K[j][d]
    float* Vs = Ks + 64 * ASTR;      // [64][68]  V^T: Vs[d][j]
    float* Ps = Vs + 64 * ASTR;      // [64][68]  P[row][j]

    const int qc = blockIdx.x, h = blockIdx.y, b = blockIdx.z;
    const int tid = threadIdx.x, lane = tid & 31, w = tid >> 5;
    const int g4 = lane >> 2, t4 = lane & 3;

    const size_t head = (size_t)(b * NH + h) * NS * NDK;
    const float* qb = q + head;
    const float* kb = k + head;
    const float* vb = v + head;

    uint32_t qa[8][4];
    {
        const int r0 = qc * 64 + w * 16 + g4;
        #pragma unroll
        for (int kk = 0; kk < 8; kk++) {
            int c0 = kk * 8 + t4;
            qa[kk][0] = to_tf32(qb[(size_t)r0 * 64 + c0] * 0.125f);
            qa[kk][1] = to_tf32(qb[(size_t)(r0 + 8) * 64 + c0] * 0.125f);
            qa[kk][2] = to_tf32(qb[(size_t)r0 * 64 + c0 + 4] * 0.125f);
            qa[kk][3] = to_tf32(qb[(size_t)(r0 + 8) * 64 + c0 + 4] * 0.125f);
        }
    }

    const float slope = exp2f(-0.5f * (float)(h + 1));
    float oacc[8][4];
    #pragma unroll
    for (int dt = 0; dt < 8; dt++)
        #pragma unroll
        for (int c = 0; c < 4; c++) oacc[dt][c] = 0.f;
    float mrow[2] = { -1e30f, -1e30f };
    float lrow[2] = { 0.f, 0.f };

    const int lrow_ld = tid >> 1, lcol0 = (tid & 1) * 32;

    for (int kc = 0; kc <= qc; kc++) {
        {
            const float* ksrc = kb + (size_t)(kc * 64 + lrow_ld) * 64 + lcol0;
            const float* vsrc = vb + (size_t)(kc * 64 + lrow_ld) * 64 + lcol0;
            float* kd = Ks + lrow_ld * ASTR + lcol0;
            #pragma unroll
            for (int c = 0; c < 32; c += 4) {
                float4 t = *(const float4*)(ksrc + c);
                *(float4*)(kd + c) = t;
                float4 tv = *(const float4*)(vsrc + c);
                Vs[(lcol0 + c + 0) * ASTR + lrow_ld] = tv.x;
                Vs[(lcol0 + c + 1) * ASTR + lrow_ld] = tv.y;
                Vs[(lcol0 + c + 2) * ASTR + lrow_ld] = tv.z;
                Vs[(lcol0 + c + 3) * ASTR + lrow_ld] = tv.w;
            }
        }
        __syncthreads();

        float sc[8][4];
        #pragma unroll
        for (int nt = 0; nt < 8; nt++) {
            sc[nt][0] = sc[nt][1] = sc[nt][2] = sc[nt][3] = 0.f;
            #pragma unroll
            for (int kk = 0; kk < 8; kk++) {
                const float* kp = &Ks[(nt * 8 + g4) * ASTR + kk * 8 + t4];
                uint32_t b0 = to_tf32(kp[0]);
                uint32_t b1 = to_tf32(kp[4]);
                MMA_TF32(sc[nt], qa[kk], b0, b1);
            }
        }

        const bool diag = (kc == qc);
        #pragma unroll
        for (int half = 0; half < 2; half++) {
            const int wr = w * 16 + g4 + half * 8;
            const int ig = qc * 64 + wr;
            float mx = -1e30f;
            #pragma unroll
            for (int nt = 0; nt < 8; nt++) {
                #pragma unroll
                for (int e = 0; e < 2; e++) {
                    int jl = nt * 8 + t4 * 2 + e;
                    int jg = kc * 64 + jl;
                    float val = sc[nt][half * 2 + e] + slope * (float)jg;
                    if (diag && jg > ig) val -= 1e9f;
                    sc[nt][half * 2 + e] = val;
                    mx = fmaxf(mx, val);
                }
            }
            mx = fmaxf(mx, __shfl_xor_sync(0xffffffffu, mx, 1));
            mx = fmaxf(mx, __shfl_xor_sync(0xffffffffu, mx, 2));
            float mnew = fmaxf(mrow[half], mx);
            float corr = __expf(mrow[half] - mnew);
            mrow[half] = mnew;
            float rs = 0.f;
            #pragma unroll
            for (int nt = 0; nt < 8; nt++) {
                #pragma unroll
                for (int e = 0; e < 2; e++) {
                    float p = __expf(sc[nt][half * 2 + e] - mnew);
                    rs += p;
                    Ps[wr * ASTR + nt * 8 + t4 * 2 + e] = p;
                }
            }
            rs += __shfl_xor_sync(0xffffffffu, rs, 1);
            rs += __shfl_xor_sync(0xffffffffu, rs, 2);
            lrow[half] = lrow[half] * corr + rs;
            #pragma unroll
            for (int dt = 0; dt < 8; dt++) {
                oacc[dt][half * 2]     *= corr;
                oacc[dt][half * 2 + 1] *= corr;
            }
        }
        __syncwarp();

        #pragma unroll
        for (int kk = 0; kk < 8; kk++) {
            uint32_t pa[4];
            const int pr = w * 16 + g4;
            pa[0] = to_tf32(Ps[pr * ASTR + kk * 8 + t4]);
            pa[1] = to_tf32(Ps[(pr + 8) * ASTR + kk * 8 + t4]);
            pa[2] = to_tf32(Ps[pr * ASTR + kk * 8 + t4 + 4]);
            pa[3] = to_tf32(Ps[(pr + 8) * ASTR + kk * 8 + t4 + 4]);
            #pragma unroll
            for (int dt = 0; dt < 8; dt++) {
                const float* vp = &Vs[(dt * 8 + g4) * ASTR + kk * 8 + t4];
                uint32_t b0 = to_tf32(vp[0]);
                uint32_t b1 = to_tf32(vp[4]);
                MMA_TF32(oacc[dt], pa, b0, b1);
            }
        }
        __syncthreads();
    }

    // epilogue: write fp32 o to [B,S,H*DK]
    #pragma unroll
    for (int half = 0; half < 2; half++) {
        const int sg = qc * 64 + w * 16 + g4 + half * 8;
        const float inv = 1.0f / lrow[half];
        const size_t base = (size_t)(b * NS + sg) * (NH * NDK) + h * NDK;
        #pragma unroll
        for (int dt = 0; dt < 8; dt++) {
            int d = dt * 8 + t4 * 2;
            float v0 = oacc[dt][half * 2]     * inv;
            float v1 = oacc[dt][half * 2 + 1] * inv;
            *(float2*)&o[base + d] = make_float2(v0, v1);
        }
    }
}

// ---------------- launcher ----------------------------------------------------
extern "C" void kernel_launch(void* const* d_in, const int* in_sizes, int n_in,
                              void* d_out, int out_size)
{
    const float* z   = (const float*)d_in[0];
    const float* r   = (const float*)d_in[1];
    const float* dwn = (const float*)d_in[2];
    const float* dbn = (const float*)d_in[3];
    const float* lng = (const float*)d_in[4];
    const float* lnb = (const float*)d_in[5];
    const float* wq  = (const float*)d_in[6];
    const float* bq  = (const float*)d_in[7];
    const float* wk  = (const float*)d_in[8];
    const float* bk  = (const float*)d_in[9];
    const float* wv  = (const float*)d_in[10];
    const float* bv  = (const float*)d_in[11];
    const float* wo  = (const float*)d_in[12];
    const float* bo  = (const float*)d_in[13];
    const float* dcw = (const float*)d_in[14];
    const float* dcb = (const float*)d_in[15];
    float* out = (float*)d_out;

    float *xcat, *x, *xn, *q, *k, *v, *o, *x2, *wpad;
    cudaGetSymbolAddress((void**)&xcat, g_xcat);
    cudaGetSymbolAddress((void**)&x,    g_x);
    cudaGetSymbolAddress((void**)&xn,   g_xn);
    cudaGetSymbolAddress((void**)&q,    g_q);
    cudaGetSymbolAddress((void**)&k,    g_k);
    cudaGetSymbolAddress((void**)&v,    g_v);
    cudaGetSymbolAddress((void**)&o,    g_o);
    cudaGetSymbolAddress((void**)&x2,   g_x2);
    cudaGetSymbolAddress((void**)&wpad, g_wpad);

    cudaFuncSetAttribute(gemm_tf32<0>, cudaFuncAttributeMaxDynamicSharedMemorySize, GEMM_SMEM);
    cudaFuncSetAttribute(gemm_tf32<1>, cudaFuncAttributeMaxDynamicSharedMemorySize, GEMM_SMEM);
    cudaFuncSetAttribute(gemm_tf32<2>, cudaFuncAttributeMaxDynamicSharedMemorySize, GEMM_SMEM);
    cudaFuncSetAttribute(attn_tc,      cudaFuncAttributeMaxDynamicSharedMemorySize, ATTN_SMEM);

    concat_k<<<(MROWS * KP + 255) / 256, 256>>>(r, z, xcat);
    wpad_k<<<(FDEC * KP + 255) / 256, 256>>>(dwn, wpad);

    dim3 ggrid(8, 64);
    gemm_tf32<0><<<ggrid, 256, GEMM_SMEM>>>(xcat, wpad, dbn, nullptr, x);
    ln_k<<<MROWS, 256>>>(x, lng, lnb, xn);
    gemm_tf32<1><<<ggrid, 256, GEMM_SMEM>>>(xn, wq, bq, nullptr, q);
    gemm_tf32<1><<<ggrid, 256, GEMM_SMEM>>>(xn, wk, bk, nullptr, k);
    gemm_tf32<1><<<ggrid, 256, GEMM_SMEM>>>(xn, wv, bv, nullptr, v);
    attn_tc<<<dim3(NS / 64, NH, NB), 128, ATTN_SMEM>>>(q, k, v, o);
    gemm_tf32<2><<<ggrid, 256, GEMM_SMEM>>>(o, wo, bo, x, x2);
    dec_k<<<MROWS, 512>>>(x2, dcw, dcb, out);
}